// round 16
// baseline (speedup 1.0000x reference)
#include <cuda_runtime.h>
#include <cuda_fp16.h>
#include <cstdint>

#define Bz  2
#define Sz  1024
#define Dz  2048
#define Hz  16
#define DHz 128
#define DFFz 8192
#define NX   (Bz*Sz*Dz)
#define NQ   (Bz*Hz*Sz*DHz)
#define NSC  33554432
#define NFF  (Bz*Sz*DFFz)
#define NW_H (Hz*Dz*DHz)
#define NW_P (Dz*Dz)
#define NW_F (Dz*DFFz)

typedef __half half_t;

// ---------------- scratch (device globals; no allocation allowed) ----------
__device__ __align__(16) float g_sc[NSC];
__device__ __align__(16) float g_t[NX], g_r1[NX], g_r2[NX];
__device__ __align__(16) float2 g_part[32*8*Sz];               // softmax partial (max,sum)
__device__ __align__(16) half_t g_xh[NX], g_eh[NX], g_1h[NX], g_2h[NX];
__device__ __align__(16) half_t g_qh[NQ], g_kh[NQ], g_vh[NQ];  // v natural [z][S][DH]
__device__ __align__(16) half_t g_ah[NSC];
__device__ __align__(16) half_t g_ch[NX];
__device__ __align__(16) half_t g_fh[NFF];
__device__ __align__(16) half_t g_w1c[3*NW_H], g_w2c[3*NW_H];  // natural [H][D][DH]
__device__ __align__(16) half_t g_pc[2*NW_P];                  // wp1,wp2 natural [D][D]
__device__ __align__(16) half_t g_Fc[2*NW_F];                  // wff1 [D][DFF], wff2 [DFF][D]

// ---------------- PTX helpers ----------------
__device__ __forceinline__ uint32_t s2u(const void* p){
    uint32_t a; asm("{ .reg .u64 t; cvta.to.shared.u64 t,%1; cvt.u32.u64 %0,t; }":"=r"(a):"l"(p)); return a;
}
__device__ __forceinline__ void cpa(uint32_t d,const void* s){
    asm volatile("cp.async.cg.shared.global [%0], [%1], 16;"::"r"(d),"l"(s));
}
#define CP_COMMIT() asm volatile("cp.async.commit_group;":::"memory")
__device__ __forceinline__ void cp_w0(){ asm volatile("cp.async.wait_group 0;":::"memory"); }
__device__ __forceinline__ void cp_w3(){ asm volatile("cp.async.wait_group 3;":::"memory"); }

__device__ __forceinline__ void ldm4(uint32_t* r, uint32_t addr){
    asm volatile("ldmatrix.sync.aligned.m8n8.x4.shared.b16 {%0,%1,%2,%3}, [%4];"
        : "=r"(r[0]),"=r"(r[1]),"=r"(r[2]),"=r"(r[3]) : "r"(addr));
}
__device__ __forceinline__ void ldm4t(uint32_t* r, uint32_t addr){
    asm volatile("ldmatrix.sync.aligned.m8n8.x4.trans.shared.b16 {%0,%1,%2,%3}, [%4];"
        : "=r"(r[0]),"=r"(r[1]),"=r"(r[2]),"=r"(r[3]) : "r"(addr));
}
__device__ __forceinline__ void mma16816(float* c, const uint32_t* a, const uint32_t* b){
    asm volatile("mma.sync.aligned.m16n8k16.row.col.f32.f16.f16.f32 "
        "{%0,%1,%2,%3}, {%4,%5,%6,%7}, {%8,%9}, {%0,%1,%2,%3};"
        : "+f"(c[0]),"+f"(c[1]),"+f"(c[2]),"+f"(c[3])
        : "r"(a[0]),"r"(a[1]),"r"(a[2]),"r"(a[3]), "r"(b[0]),"r"(b[1]));
}

// A-style tile: 128 rows x 32 halves, 80B row stride
__device__ __forceinline__ void fill_a(uint32_t dst, const half_t* g, int ld, int k0, int tid){
#pragma unroll
    for(int i=0;i<2;i++){
        int c = tid + i*256;
        int r = c>>2, ch = c&3;
        cpa(dst + r*80 + ch*16, (const char*)(g + (size_t)r*ld + k0) + ch*16);
    }
}
// TRB tile: 32 k-rows x 128 halves, 272B row stride; g pre-offset by n0
__device__ __forceinline__ void fill_bt(uint32_t dst, const half_t* g, int ld, int k0, int tid){
#pragma unroll
    for(int i=0;i<2;i++){
        int c = tid + i*256;
        int r = c>>4, ch = c&15;
        cpa(dst + r*272 + ch*16, (const char*)(g + (size_t)(k0+r)*ld) + ch*16);
    }
}

// ---------------- core mma.sync GEMM: C[128x128] tile ----------------------
// A row-major [M,K]; B: TRB? [K,N] natural (ldb = N row stride) : [N,K] (ldb = K row stride).
// 256 threads, 8 warps 2(m) x 4(n), warp tile 64x32.  5-stage cp.async pipeline.
// EPI: 0=fp32 C; 1=fp16 C.  STATS: emit per-column online (max,sum) over this
// CTA's 128 rows into part[n0..n0+127].
template<int EPI,bool RELU,bool BIAS,bool TRB,bool STATS>
__device__ __forceinline__ void mm(
    const half_t* __restrict__ A,int lda,
    const half_t* __restrict__ B,int ldb,
    const float* __restrict__ bias,float alpha,
    float* __restrict__ C, half_t* __restrict__ Ch, long ldc,
    int K,int m0,int n0, float2* __restrict__ part)
{
    extern __shared__ __align__(16) char smem[];   // 5 stages x 20480
    uint32_t sb = s2u(smem);
    const int tid = threadIdx.x, lane = tid & 31, wid = tid >> 5;
    const int wm = wid & 1, wn = wid >> 1;

    A += (size_t)m0 * lda;
    B += TRB ? (size_t)n0 : (size_t)n0 * ldb;

    float acc[4][4][4];
#pragma unroll
    for(int i=0;i<4;i++)
#pragma unroll
        for(int j=0;j<4;j++)
#pragma unroll
            for(int q=0;q<4;q++) acc[i][j][q]=0.f;

    const int num = K >> 5;   // >= 4 for every shape in this problem
    // prologue: fill stages 0..3 (one commit each; commit count stays uniform)
#pragma unroll
    for(int s=0;s<4;s++){
        if(s<num){
            uint32_t st = sb + (uint32_t)s*20480;
            fill_a(st, A, lda, s<<5, tid);
            if(TRB) fill_bt(st+10240, B, ldb, s<<5, tid);
            else    fill_a (st+10240, B, ldb, s<<5, tid);
        }
        CP_COMMIT();
    }

    const uint32_t a_base = (uint32_t)((wm*64 + (lane&15))*80 + (lane>>4)*16);
    const uint32_t b_base = (uint32_t)((wn*32 + (lane&7) + ((lane>>4)<<3))*80 + ((lane>>3)&1)*16);
    const uint32_t bt_row = (uint32_t)(((lane>>3)&1)*8 + (lane&7));
    const uint32_t bt_col = (uint32_t)(wn*32 + ((lane>>4)<<3));

    for(int c=0;c<num;c++){
        cp_w3();                       // <=3 newer groups pending => chunk c resident
        __syncthreads();               // also protects stage (c+4)%5 refill below
        if(c+4<num){
            uint32_t nb = sb + (uint32_t)((c+4)%5)*20480;
            int k1 = (c+4) << 5;
            fill_a(nb, A, lda, k1, tid);
            if(TRB) fill_bt(nb+10240, B, ldb, k1, tid);
            else    fill_a (nb+10240, B, ldb, k1, tid);
        }
        CP_COMMIT();                   // uniform one commit per iteration

        uint32_t st = sb + (uint32_t)(c%5)*20480;
        uint32_t aoff = st + a_base;
#pragma unroll
        for(int ks=0;ks<2;ks++){
            uint32_t af[4][4], bf[4][2], bt[4];
#pragma unroll
            for(int mf=0;mf<4;mf++) ldm4(af[mf], aoff + mf*1280 + ks*32);
            if(TRB){
                uint32_t bo = st + 10240 + (ks*16 + bt_row)*272 + bt_col*2;
                ldm4t(bt, bo);
                bf[0][0]=bt[0]; bf[0][1]=bt[1]; bf[1][0]=bt[2]; bf[1][1]=bt[3];
                ldm4t(bt, bo + 32);   // +16 n-cols
                bf[2][0]=bt[0]; bf[2][1]=bt[1]; bf[3][0]=bt[2]; bf[3][1]=bt[3];
            } else {
                uint32_t bo = st + 10240 + b_base;
                ldm4(bt, bo + ks*32);
                bf[0][0]=bt[0]; bf[0][1]=bt[1]; bf[1][0]=bt[2]; bf[1][1]=bt[3];
                ldm4(bt, bo + 1280 + ks*32);
                bf[2][0]=bt[0]; bf[2][1]=bt[1]; bf[3][0]=bt[2]; bf[3][1]=bt[3];
            }
#pragma unroll
            for(int mf=0;mf<4;mf++)
#pragma unroll
                for(int nf=0;nf<4;nf++) mma16816(acc[mf][nf], af[mf], bf[nf]);
        }
        // no trailing barrier: next iteration's top barrier precedes any refill
        // of the stage this iteration just read.
    }

    // epilogue: write C
#pragma unroll
    for(int mf=0;mf<4;mf++){
#pragma unroll
        for(int nf=0;nf<4;nf++){
            int r  = m0 + wm*64 + mf*16 + (lane>>2);
            int cc = n0 + wn*32 + nf*8  + (lane&3)*2;
            float v0=acc[mf][nf][0]*alpha, v1=acc[mf][nf][1]*alpha;
            float v2=acc[mf][nf][2]*alpha, v3=acc[mf][nf][3]*alpha;
            if(BIAS){ float b0=bias[cc], b1=bias[cc+1]; v0+=b0; v1+=b1; v2+=b0; v3+=b1; }
            if(RELU){ v0=fmaxf(v0,0.f); v1=fmaxf(v1,0.f); v2=fmaxf(v2,0.f); v3=fmaxf(v3,0.f); }
            if(EPI==0){
                *(float2*)(C + (size_t)r*ldc + cc)     = make_float2(v0,v1);
                *(float2*)(C + (size_t)(r+8)*ldc + cc) = make_float2(v2,v3);
            } else {
                *(__half2*)(Ch + (size_t)r*ldc + cc)     = __floats2half2_rn(v0,v1);
                *(__half2*)(Ch + (size_t)(r+8)*ldc + cc) = __floats2half2_rn(v2,v3);
            }
        }
    }

    if(STATS){
        // column-wise online (max,sum) over this CTA's 128 rows.
        cp_w0();                               // drain async before reusing smem
        __syncthreads();
        float2* st2 = (float2*)smem;           // [2][128]
        float sm_[4][2], ss_[4][2];
#pragma unroll
        for(int nf=0;nf<4;nf++){
#pragma unroll
            for(int j=0;j<2;j++){
                float m=-1e30f,s=0.f;
#pragma unroll
                for(int mf=0;mf<4;mf++){
#pragma unroll
                    for(int h=0;h<2;h++){
                        float v=acc[mf][nf][j+2*h]*alpha;
                        float nm=fmaxf(m,v);
                        s=s*__expf(m-nm)+__expf(v-nm); m=nm;
                    }
                }
                sm_[nf][j]=m; ss_[nf][j]=s;
            }
        }
        // merge the 8 row-groups within the warp (lane bits 2..4), col in lane&3
#pragma unroll
        for(int nf=0;nf<4;nf++){
#pragma unroll
            for(int j=0;j<2;j++){
                float m=sm_[nf][j], s=ss_[nf][j];
#pragma unroll
                for(int o=4;o<=16;o<<=1){
                    float om=__shfl_xor_sync(0xffffffffu,m,o);
                    float os=__shfl_xor_sync(0xffffffffu,s,o);
                    float nm=fmaxf(m,om);
                    s=s*__expf(m-nm)+os*__expf(om-nm); m=nm;
                }
                if((lane>>2)==0)
                    st2[wm*128 + wn*32 + nf*8 + (lane&3)*2 + j]=make_float2(m,s);
            }
        }
        __syncthreads();
        if(tid<128){
            float2 a0=st2[tid], a1=st2[128+tid];
            float nm=fmaxf(a0.x,a1.x);
            float s=a0.y*__expf(a0.x-nm)+a1.y*__expf(a1.x-nm);
            part[n0+tid]=make_float2(nm,s);
        }
    }
}

#define SMB (5*20480)

// ---------------- GEMM wrapper kernels ----------------
// fused QKV projection: grid (8, 3, 32); y: 0=Q (input xq), 1=K, 2=V (input xkv)
__global__ void __launch_bounds__(256)
k_proj3(const half_t* xq,const half_t* xkv,const half_t* w,
        const float* bq,const float* bk,const float* bv,
        half_t* oq,half_t* ok,half_t* ov){
    int which=blockIdx.y;
    int z=blockIdx.z,b=z>>4,h=z&15;
    const half_t* A = (which==0)?xq:xkv;
    const float* bias = (which==0)?bq:((which==1)?bk:bv);
    half_t* o = (which==0)?oq:((which==1)?ok:ov);
    mm<1,false,true,true,false>(A+(size_t)b*Sz*Dz,Dz,
        w+(size_t)which*NW_H+(size_t)h*Dz*DHz,DHz,
        bias+h*DHz,1.0f, nullptr,o+(size_t)z*Sz*DHz,DHz, Dz, blockIdx.x*128,0, nullptr);
}
// scores + fused per-tile softmax stats
__global__ void __launch_bounds__(256)
k_scores(const half_t* q,const half_t* k,float* sc,float2* part){
    size_t z=blockIdx.z;
    mm<0,false,false,false,true>(q+z*Sz*DHz,DHz, k+z*Sz*DHz,DHz,
        nullptr,0.08838834764831845f, sc+z*Sz*Sz,nullptr,Sz, DHz,
        blockIdx.x*128, blockIdx.y*128,
        part + ((size_t)z*8 + blockIdx.x)*Sz);
}
__global__ void __launch_bounds__(256)
k_attnv(const half_t* a,const half_t* v,half_t* cat){
    size_t z=blockIdx.z; int b=blockIdx.z>>4,h=blockIdx.z&15;
    mm<1,false,false,true,false>(a+z*Sz*Sz,Sz, v+z*Sz*DHz,DHz,
        nullptr,1.0f, nullptr,cat+(size_t)b*Sz*Dz+h*DHz,Dz, Sz, blockIdx.x*128,0, nullptr);
}
__global__ void __launch_bounds__(256)
k_lin32(const half_t* a,int lda,const half_t* b,int ldb,
        const float* bias,float* C,int ldc,int K){
    mm<0,false,true,true,false>(a,lda,b,ldb,bias,1.0f,C,nullptr,ldc,K,
        blockIdx.x*128, blockIdx.y*128, nullptr);
}
__global__ void __launch_bounds__(256)
k_linrelu(const half_t* a,int lda,const half_t* b,int ldb,
          const float* bias,half_t* Ch,int ldc,int K){
    mm<1,true,true,true,false>(a,lda,b,ldb,bias,1.0f,nullptr,Ch,ldc,K,
        blockIdx.x*128, blockIdx.y*128, nullptr);
}

// ---------------- conversions (single launch) ----------------
struct CvtArgs {
    const float4* in[12];
    __half2* out[12];
    int n4[12];
};
__global__ void __launch_bounds__(256)
k_hall(CvtArgs a){
    int seg = blockIdx.y;
    const float4* in = a.in[seg];
    __half2* o = a.out[seg];
    int n4 = a.n4[seg];
    for(int i=blockIdx.x*256+threadIdx.x; i<n4; i+=gridDim.x*256){
        float4 v=in[i];
        o[2*i]   = __floats2half2_rn(v.x,v.y);
        o[2*i+1] = __floats2half2_rn(v.z,v.w);
    }
}

// ---------------- softmax normalize: parallel, register-resident stats -----
// grid (32, 32): CTA = 32-row chunk of one z; thread owns 4 columns.
__global__ void __launch_bounds__(256)
k_smnorm(const float* __restrict__ sc, const float2* __restrict__ part,
         half_t* __restrict__ o){
    int z=blockIdx.y, rc=blockIdx.x;
    int c0=threadIdx.x*4;
    float m[4], inv[4];
#pragma unroll
    for(int j=0;j<4;j++){
        float mm=-1e30f,s=0.f;
#pragma unroll
        for(int k=0;k<8;k++){
            float2 ps=part[((size_t)z*8+k)*Sz+c0+j];
            float nm=fmaxf(mm,ps.x);
            s=s*__expf(mm-nm)+ps.y*__expf(ps.x-nm);
            mm=nm;
        }
        m[j]=mm; inv[j]=1.0f/s;
    }
    size_t base=(size_t)z*Sz*Sz+(size_t)rc*32*Sz+c0;
#pragma unroll 4
    for(int r=0;r<32;r++){
        size_t ro=base+(size_t)r*Sz;
        float4 v=*(const float4*)(sc+ro);
        __half2 h0=__floats2half2_rn(__expf(v.x-m[0])*inv[0], __expf(v.y-m[1])*inv[1]);
        __half2 h1=__floats2half2_rn(__expf(v.z-m[2])*inv[2], __expf(v.w-m[3])*inv[3]);
        uint2 w;
        w.x=*(uint32_t*)&h0; w.y=*(uint32_t*)&h1;
        *(uint2*)(o+ro)=w;
    }
}

__global__ void __launch_bounds__(256)
k_addln(const float* __restrict__ xa,const float* __restrict__ xb,
        const float* __restrict__ gg,const float* __restrict__ bb,
        float* __restrict__ out, half_t* __restrict__ oh){
    int row=blockIdx.x;
    const float* xr=xa+(size_t)row*Dz;
    const float* yr=xb+(size_t)row*Dz;
    float v[8]; float s=0.f,s2=0.f;
#pragma unroll
    for(int i=0;i<8;i++){ int c=threadIdx.x+i*256; v[i]=xr[c]+yr[c]; s+=v[i]; s2+=v[i]*v[i]; }
    __shared__ float rs[8],rs2[8];
#pragma unroll
    for(int o=16;o>0;o>>=1){ s+=__shfl_xor_sync(0xffffffffu,s,o); s2+=__shfl_xor_sync(0xffffffffu,s2,o); }
    int wid=threadIdx.x>>5,lid=threadIdx.x&31;
    if(lid==0){ rs[wid]=s; rs2[wid]=s2; }
    __syncthreads();
    if(threadIdx.x<32){
        s=(threadIdx.x<8)?rs[threadIdx.x]:0.f; s2=(threadIdx.x<8)?rs2[threadIdx.x]:0.f;
#pragma unroll
        for(int o=4;o>0;o>>=1){ s+=__shfl_xor_sync(0xffffffffu,s,o); s2+=__shfl_xor_sync(0xffffffffu,s2,o); }
        if(threadIdx.x==0){ rs[0]=s; rs2[0]=s2; }
    }
    __syncthreads();
    float mean=rs[0]*(1.0f/Dz);
    float var=rs2[0]*(1.0f/Dz)-mean*mean;
    float inv=rsqrtf(var+1e-5f);
#pragma unroll
    for(int i=0;i<8;i++){
        int c=threadIdx.x+i*256;
        float o=(v[i]-mean)*inv*gg[c]+bb[c];
        out[(size_t)row*Dz+c]=o;
        if(oh) oh[(size_t)row*Dz+c]=__float2half_rn(o);
    }
}

// ---------------- launch ----------------
#define GA(v,s) do{ void* _p; cudaGetSymbolAddress(&_p,s); v=(decltype(v))_p; }while(0)

extern "C" void kernel_launch(void* const* d_in,const int* in_sizes,int n_in,
                              void* d_out,int out_size)
{
    const float* x   =(const float*)d_in[0];
    const float* enc =(const float*)d_in[1];
    const float* wq1 =(const float*)d_in[2];
    const float* wk1 =(const float*)d_in[3];
    const float* wv1 =(const float*)d_in[4];
    const float* bq1 =(const float*)d_in[5];
    const float* bk1 =(const float*)d_in[6];
    const float* bv1 =(const float*)d_in[7];
    const float* wp1 =(const float*)d_in[8];
    const float* bp1 =(const float*)d_in[9];
    const float* wq2 =(const float*)d_in[10];
    const float* wk2 =(const float*)d_in[11];
    const float* wv2 =(const float*)d_in[12];
    const float* bq2 =(const float*)d_in[13];
    const float* bk2 =(const float*)d_in[14];
    const float* bv2 =(const float*)d_in[15];
    const float* wp2 =(const float*)d_in[16];
    const float* bp2 =(const float*)d_in[17];
    const float* ln1g=(const float*)d_in[18];
    const float* ln1b=(const float*)d_in[19];
    const float* ln2g=(const float*)d_in[20];
    const float* ln2b=(const float*)d_in[21];
    const float* ln3g=(const float*)d_in[22];
    const float* ln3b=(const float*)d_in[23];
    const float* wff1=(const float*)d_in[24];
    const float* bff1=(const float*)d_in[25];
    const float* wff2=(const float*)d_in[26];
    const float* bff2=(const float*)d_in[27];
    float* out=(float*)d_out;

    float *sc,*tp,*r1,*r2; float2* part;
    half_t *xh,*eh,*h1,*h2,*qh,*kh,*vh,*ah,*ch,*fh,*w1,*w2,*pc,*Fc;
    GA(sc,g_sc); GA(tp,g_t); GA(r1,g_r1); GA(r2,g_r2); GA(part,g_part);
    GA(xh,g_xh); GA(eh,g_eh); GA(h1,g_1h); GA(h2,g_2h);
    GA(qh,g_qh); GA(kh,g_kh); GA(vh,g_vh); GA(ah,g_ah);
    GA(ch,g_ch); GA(fh,g_fh);
    GA(w1,g_w1c); GA(w2,g_w2c); GA(pc,g_pc); GA(Fc,g_Fc);

    cudaFuncSetAttribute(k_proj3,  cudaFuncAttributeMaxDynamicSharedMemorySize,SMB);
    cudaFuncSetAttribute(k_scores, cudaFuncAttributeMaxDynamicSharedMemorySize,SMB);
    cudaFuncSetAttribute(k_attnv,  cudaFuncAttributeMaxDynamicSharedMemorySize,SMB);
    cudaFuncSetAttribute(k_lin32,  cudaFuncAttributeMaxDynamicSharedMemorySize,SMB);
    cudaFuncSetAttribute(k_linrelu,cudaFuncAttributeMaxDynamicSharedMemorySize,SMB);

    // all fp32->fp16 casts in ONE launch
    CvtArgs ca;
    ca.in[0]=(const float4*)wq1;  ca.out[0]=(__half2*)w1;           ca.n4[0]=NW_H/4;
    ca.in[1]=(const float4*)wk1;  ca.out[1]=(__half2*)(w1+NW_H);    ca.n4[1]=NW_H/4;
    ca.in[2]=(const float4*)wv1;  ca.out[2]=(__half2*)(w1+2*NW_H);  ca.n4[2]=NW_H/4;
    ca.in[3]=(const float4*)wq2;  ca.out[3]=(__half2*)w2;           ca.n4[3]=NW_H/4;
    ca.in[4]=(const float4*)wk2;  ca.out[4]=(__half2*)(w2+NW_H);    ca.n4[4]=NW_H/4;
    ca.in[5]=(const float4*)wv2;  ca.out[5]=(__half2*)(w2+2*NW_H);  ca.n4[5]=NW_H/4;
    ca.in[6]=(const float4*)wp1;  ca.out[6]=(__half2*)pc;           ca.n4[6]=NW_P/4;
    ca.in[7]=(const float4*)wp2;  ca.out[7]=(__half2*)(pc+NW_P);    ca.n4[7]=NW_P/4;
    ca.in[8]=(const float4*)wff1; ca.out[8]=(__half2*)Fc;           ca.n4[8]=NW_F/4;
    ca.in[9]=(const float4*)wff2; ca.out[9]=(__half2*)(Fc+NW_F);    ca.n4[9]=NW_F/4;
    ca.in[10]=(const float4*)x;   ca.out[10]=(__half2*)xh;          ca.n4[10]=NX/4;
    ca.in[11]=(const float4*)enc; ca.out[11]=(__half2*)eh;          ca.n4[11]=NX/4;
    k_hall<<<dim3(512,12),256>>>(ca);

    dim3 gp3(Sz/128,3,Bz*Hz), gp(Sz/128,1,Bz*Hz), gs(Sz/128,Sz/128,Bz*Hz);
    dim3 gsm(32,Bz*Hz);
    dim3 gpp(2*Sz/128,Dz/128), gf1(2*Sz/128,DFFz/128);

    // ---- self attention ----
    k_proj3<<<gp3,256,SMB>>>(xh,xh,w1,bq1,bk1,bv1,qh,kh,vh);
    k_scores<<<gs,256,SMB>>>(qh,kh,sc,part);
    k_smnorm<<<gsm,256>>>(sc,part,ah);
    k_attnv<<<gp,256,SMB>>>(ah,vh,ch);
    k_lin32<<<gpp,256,SMB>>>(ch,Dz,pc,Dz,bp1,tp,Dz,Dz);
    k_addln<<<Bz*Sz,256>>>(x,tp,ln1g,ln1b,r1,h1);

    // ---- cross attention: q from encoder_output, k/v from x1 ----
    k_proj3<<<gp3,256,SMB>>>(eh,h1,w2,bq2,bk2,bv2,qh,kh,vh);
    k_scores<<<gs,256,SMB>>>(qh,kh,sc,part);
    k_smnorm<<<gsm,256>>>(sc,part,ah);
    k_attnv<<<gp,256,SMB>>>(ah,vh,ch);
    k_lin32<<<gpp,256,SMB>>>(ch,Dz,pc+NW_P,Dz,bp2,tp,Dz,Dz);
    k_addln<<<Bz*Sz,256>>>(r1,tp,ln2g,ln2b,r2,h2);

    // ---- feed forward (ldb = natural row stride of B: wff1->DFFz, wff2->Dz) ----
    k_linrelu<<<gf1,256,SMB>>>(h2,Dz,Fc,DFFz,bff1,fh,DFFz,Dz);
    k_lin32<<<gpp,256,SMB>>>(fh,DFFz,Fc+NW_F,Dz,bff2,tp,Dz,DFFz);
    k_addln<<<Bz*Sz,256>>>(r2,tp,ln3g,ln3b,out,nullptr);
}

// round 17
// speedup vs baseline: 1.0491x; 1.0491x over previous
#include <cuda_runtime.h>
#include <cuda_fp16.h>
#include <cstdint>

#define Bz  2
#define Sz  1024
#define Dz  2048
#define Hz  16
#define DHz 128
#define DFFz 8192
#define NX   (Bz*Sz*Dz)
#define NQ   (Bz*Hz*Sz*DHz)
#define NSC  33554432
#define NFF  (Bz*Sz*DFFz)
#define NW_H (Hz*Dz*DHz)
#define NW_P (Dz*Dz)
#define NW_F (Dz*DFFz)

typedef __half half_t;

// ---------------- scratch (device globals; no allocation allowed) ----------
__device__ __align__(16) float g_sc[NSC];
__device__ __align__(16) float g_t[NX], g_r1[NX], g_r2[NX];
__device__ __align__(16) float2 g_part[32*8*Sz];               // softmax partial (max,sum)
__device__ __align__(16) half_t g_xh[NX], g_eh[NX], g_1h[NX], g_2h[NX];
__device__ __align__(16) half_t g_qh[NQ], g_kh[NQ], g_vh[NQ];  // v natural [z][S][DH]
__device__ __align__(16) half_t g_ah[NSC];
__device__ __align__(16) half_t g_ch[NX];
__device__ __align__(16) half_t g_fh[NFF];
__device__ __align__(16) half_t g_w1c[3*NW_H], g_w2c[3*NW_H];  // natural [H][D][DH]
__device__ __align__(16) half_t g_pc[2*NW_P];                  // wp1,wp2 natural [D][D]
__device__ __align__(16) half_t g_Fc[2*NW_F];                  // wff1 [D][DFF], wff2 [DFF][D]

// ---------------- PTX helpers ----------------
__device__ __forceinline__ uint32_t s2u(const void* p){
    uint32_t a; asm("{ .reg .u64 t; cvta.to.shared.u64 t,%1; cvt.u32.u64 %0,t; }":"=r"(a):"l"(p)); return a;
}
__device__ __forceinline__ void cpa(uint32_t d,const void* s){
    asm volatile("cp.async.cg.shared.global [%0], [%1], 16;"::"r"(d),"l"(s));
}
#define CP_COMMIT() asm volatile("cp.async.commit_group;":::"memory")
__device__ __forceinline__ void cp_w0(){ asm volatile("cp.async.wait_group 0;":::"memory"); }
__device__ __forceinline__ void cp_w2(){ asm volatile("cp.async.wait_group 2;":::"memory"); }

__device__ __forceinline__ void ldm4(uint32_t* r, uint32_t addr){
    asm volatile("ldmatrix.sync.aligned.m8n8.x4.shared.b16 {%0,%1,%2,%3}, [%4];"
        : "=r"(r[0]),"=r"(r[1]),"=r"(r[2]),"=r"(r[3]) : "r"(addr));
}
__device__ __forceinline__ void ldm4t(uint32_t* r, uint32_t addr){
    asm volatile("ldmatrix.sync.aligned.m8n8.x4.trans.shared.b16 {%0,%1,%2,%3}, [%4];"
        : "=r"(r[0]),"=r"(r[1]),"=r"(r[2]),"=r"(r[3]) : "r"(addr));
}
__device__ __forceinline__ void mma16816(float* c, const uint32_t* a, const uint32_t* b){
    asm volatile("mma.sync.aligned.m16n8k16.row.col.f32.f16.f16.f32 "
        "{%0,%1,%2,%3}, {%4,%5,%6,%7}, {%8,%9}, {%0,%1,%2,%3};"
        : "+f"(c[0]),"+f"(c[1]),"+f"(c[2]),"+f"(c[3])
        : "r"(a[0]),"r"(a[1]),"r"(a[2]),"r"(a[3]), "r"(b[0]),"r"(b[1]));
}

// A-style tile: 128 rows x 32 halves, 80B row stride
__device__ __forceinline__ void fill_a(uint32_t dst, const half_t* g, int ld, int k0, int tid){
#pragma unroll
    for(int i=0;i<2;i++){
        int c = tid + i*256;
        int r = c>>2, ch = c&3;
        cpa(dst + r*80 + ch*16, (const char*)(g + (size_t)r*ld + k0) + ch*16);
    }
}
// TRB tile: 32 k-rows x 128 halves, 272B row stride; g pre-offset by n0
__device__ __forceinline__ void fill_bt(uint32_t dst, const half_t* g, int ld, int k0, int tid){
#pragma unroll
    for(int i=0;i<2;i++){
        int c = tid + i*256;
        int r = c>>4, ch = c&15;
        cpa(dst + r*272 + ch*16, (const char*)(g + (size_t)(k0+r)*ld) + ch*16);
    }
}

// ---------------- core mma.sync GEMM: C[128x128] tile ----------------------
// A row-major [M,K]; B: TRB? [K,N] natural (ldb = N row stride) : [N,K] (ldb = K row stride).
// 256 threads, 8 warps 2(m) x 4(n), warp tile 64x32.  4-stage cp.async pipeline.
// EPI: 0=fp32 C; 1=fp16 C.  STATS: emit per-column online (max,sum) over this
// CTA's 128 rows into part[n0..n0+127].
template<int EPI,bool RELU,bool BIAS,bool TRB,bool STATS>
__device__ __forceinline__ void mm(
    const half_t* __restrict__ A,int lda,
    const half_t* __restrict__ B,int ldb,
    const float* __restrict__ bias,float alpha,
    float* __restrict__ C, half_t* __restrict__ Ch, long ldc,
    int K,int m0,int n0, float2* __restrict__ part)
{
    extern __shared__ __align__(16) char smem[];   // 4 stages x 20480
    uint32_t sb = s2u(smem);
    const int tid = threadIdx.x, lane = tid & 31, wid = tid >> 5;
    const int wm = wid & 1, wn = wid >> 1;

    A += (size_t)m0 * lda;
    B += TRB ? (size_t)n0 : (size_t)n0 * ldb;

    float acc[4][4][4];
#pragma unroll
    for(int i=0;i<4;i++)
#pragma unroll
        for(int j=0;j<4;j++)
#pragma unroll
            for(int q=0;q<4;q++) acc[i][j][q]=0.f;

    const int num = K >> 5;   // >= 4 for every shape in this problem
    // prologue: fill stages 0..2 (one commit each; commit count stays uniform)
#pragma unroll
    for(int s=0;s<3;s++){
        if(s<num){
            uint32_t st = sb + (uint32_t)s*20480;
            fill_a(st, A, lda, s<<5, tid);
            if(TRB) fill_bt(st+10240, B, ldb, s<<5, tid);
            else    fill_a (st+10240, B, ldb, s<<5, tid);
        }
        CP_COMMIT();
    }

    const uint32_t a_base = (uint32_t)((wm*64 + (lane&15))*80 + (lane>>4)*16);
    const uint32_t b_base = (uint32_t)((wn*32 + (lane&7) + ((lane>>4)<<3))*80 + ((lane>>3)&1)*16);
    const uint32_t bt_row = (uint32_t)(((lane>>3)&1)*8 + (lane&7));
    const uint32_t bt_col = (uint32_t)(wn*32 + ((lane>>4)<<3));

    for(int c=0;c<num;c++){
        cp_w2();                       // <=2 newer groups pending => chunk c resident
        __syncthreads();               // also protects stage (c+3)&3 refill below
        if(c+3<num){
            uint32_t nb = sb + (uint32_t)((c+3)&3)*20480;
            int k1 = (c+3) << 5;
            fill_a(nb, A, lda, k1, tid);
            if(TRB) fill_bt(nb+10240, B, ldb, k1, tid);
            else    fill_a (nb+10240, B, ldb, k1, tid);
        }
        CP_COMMIT();                   // uniform one commit per iteration

        uint32_t st = sb + (uint32_t)(c&3)*20480;
        uint32_t aoff = st + a_base;
#pragma unroll
        for(int ks=0;ks<2;ks++){
            uint32_t af[4][4], bf[4][2], bt[4];
#pragma unroll
            for(int mf=0;mf<4;mf++) ldm4(af[mf], aoff + mf*1280 + ks*32);
            if(TRB){
                uint32_t bo = st + 10240 + (ks*16 + bt_row)*272 + bt_col*2;
                ldm4t(bt, bo);
                bf[0][0]=bt[0]; bf[0][1]=bt[1]; bf[1][0]=bt[2]; bf[1][1]=bt[3];
                ldm4t(bt, bo + 32);   // +16 n-cols
                bf[2][0]=bt[0]; bf[2][1]=bt[1]; bf[3][0]=bt[2]; bf[3][1]=bt[3];
            } else {
                uint32_t bo = st + 10240 + b_base;
                ldm4(bt, bo + ks*32);
                bf[0][0]=bt[0]; bf[0][1]=bt[1]; bf[1][0]=bt[2]; bf[1][1]=bt[3];
                ldm4(bt, bo + 1280 + ks*32);
                bf[2][0]=bt[0]; bf[2][1]=bt[1]; bf[3][0]=bt[2]; bf[3][1]=bt[3];
            }
#pragma unroll
            for(int mf=0;mf<4;mf++)
#pragma unroll
                for(int nf=0;nf<4;nf++) mma16816(acc[mf][nf], af[mf], bf[nf]);
        }
        // no trailing barrier: next iteration's top barrier precedes any refill
        // of the stage this iteration just read.
    }

    // epilogue: write C
#pragma unroll
    for(int mf=0;mf<4;mf++){
#pragma unroll
        for(int nf=0;nf<4;nf++){
            int r  = m0 + wm*64 + mf*16 + (lane>>2);
            int cc = n0 + wn*32 + nf*8  + (lane&3)*2;
            float v0=acc[mf][nf][0]*alpha, v1=acc[mf][nf][1]*alpha;
            float v2=acc[mf][nf][2]*alpha, v3=acc[mf][nf][3]*alpha;
            if(BIAS){ float b0=bias[cc], b1=bias[cc+1]; v0+=b0; v1+=b1; v2+=b0; v3+=b1; }
            if(RELU){ v0=fmaxf(v0,0.f); v1=fmaxf(v1,0.f); v2=fmaxf(v2,0.f); v3=fmaxf(v3,0.f); }
            if(EPI==0){
                *(float2*)(C + (size_t)r*ldc + cc)     = make_float2(v0,v1);
                *(float2*)(C + (size_t)(r+8)*ldc + cc) = make_float2(v2,v3);
            } else {
                *(__half2*)(Ch + (size_t)r*ldc + cc)     = __floats2half2_rn(v0,v1);
                *(__half2*)(Ch + (size_t)(r+8)*ldc + cc) = __floats2half2_rn(v2,v3);
            }
        }
    }

    if(STATS){
        // column-wise online (max,sum) over this CTA's 128 rows.
        cp_w0();                               // drain async before reusing smem
        __syncthreads();
        float2* st2 = (float2*)smem;           // [2][128]
        float sm_[4][2], ss_[4][2];
#pragma unroll
        for(int nf=0;nf<4;nf++){
#pragma unroll
            for(int j=0;j<2;j++){
                float m=-1e30f,s=0.f;
#pragma unroll
                for(int mf=0;mf<4;mf++){
#pragma unroll
                    for(int h=0;h<2;h++){
                        float v=acc[mf][nf][j+2*h]*alpha;
                        float nm=fmaxf(m,v);
                        s=s*__expf(m-nm)+__expf(v-nm); m=nm;
                    }
                }
                sm_[nf][j]=m; ss_[nf][j]=s;
            }
        }
        // merge the 8 row-groups within the warp (lane bits 2..4), col in lane&3
#pragma unroll
        for(int nf=0;nf<4;nf++){
#pragma unroll
            for(int j=0;j<2;j++){
                float m=sm_[nf][j], s=ss_[nf][j];
#pragma unroll
                for(int o=4;o<=16;o<<=1){
                    float om=__shfl_xor_sync(0xffffffffu,m,o);
                    float os=__shfl_xor_sync(0xffffffffu,s,o);
                    float nm=fmaxf(m,om);
                    s=s*__expf(m-nm)+os*__expf(om-nm); m=nm;
                }
                if((lane>>2)==0)
                    st2[wm*128 + wn*32 + nf*8 + (lane&3)*2 + j]=make_float2(m,s);
            }
        }
        __syncthreads();
        if(tid<128){
            float2 a0=st2[tid], a1=st2[128+tid];
            float nm=fmaxf(a0.x,a1.x);
            float s=a0.y*__expf(a0.x-nm)+a1.y*__expf(a1.x-nm);
            part[n0+tid]=make_float2(nm,s);
        }
    }
}

#define SMB (4*20480)

// ---------------- GEMM wrapper kernels ----------------
// fused QKV projection: grid (8, 3, 32); y: 0=Q (input xq), 1=K, 2=V (input xkv)
__global__ void __launch_bounds__(256)
k_proj3(const half_t* xq,const half_t* xkv,const half_t* w,
        const float* bq,const float* bk,const float* bv,
        half_t* oq,half_t* ok,half_t* ov){
    int which=blockIdx.y;
    int z=blockIdx.z,b=z>>4,h=z&15;
    const half_t* A = (which==0)?xq:xkv;
    const float* bias = (which==0)?bq:((which==1)?bk:bv);
    half_t* o = (which==0)?oq:((which==1)?ok:ov);
    mm<1,false,true,true,false>(A+(size_t)b*Sz*Dz,Dz,
        w+(size_t)which*NW_H+(size_t)h*Dz*DHz,DHz,
        bias+h*DHz,1.0f, nullptr,o+(size_t)z*Sz*DHz,DHz, Dz, blockIdx.x*128,0, nullptr);
}
// scores + fused per-tile softmax stats
__global__ void __launch_bounds__(256)
k_scores(const half_t* q,const half_t* k,float* sc,float2* part){
    size_t z=blockIdx.z;
    mm<0,false,false,false,true>(q+z*Sz*DHz,DHz, k+z*Sz*DHz,DHz,
        nullptr,0.08838834764831845f, sc+z*Sz*Sz,nullptr,Sz, DHz,
        blockIdx.x*128, blockIdx.y*128,
        part + ((size_t)z*8 + blockIdx.x)*Sz);
}
__global__ void __launch_bounds__(256)
k_attnv(const half_t* a,const half_t* v,half_t* cat){
    size_t z=blockIdx.z; int b=blockIdx.z>>4,h=blockIdx.z&15;
    mm<1,false,false,true,false>(a+z*Sz*Sz,Sz, v+z*Sz*DHz,DHz,
        nullptr,1.0f, nullptr,cat+(size_t)b*Sz*Dz+h*DHz,Dz, Sz, blockIdx.x*128,0, nullptr);
}
__global__ void __launch_bounds__(256)
k_lin32(const half_t* a,int lda,const half_t* b,int ldb,
        const float* bias,float* C,int ldc,int K){
    mm<0,false,true,true,false>(a,lda,b,ldb,bias,1.0f,C,nullptr,ldc,K,
        blockIdx.x*128, blockIdx.y*128, nullptr);
}
__global__ void __launch_bounds__(256)
k_linrelu(const half_t* a,int lda,const half_t* b,int ldb,
          const float* bias,half_t* Ch,int ldc,int K){
    mm<1,true,true,true,false>(a,lda,b,ldb,bias,1.0f,nullptr,Ch,ldc,K,
        blockIdx.x*128, blockIdx.y*128, nullptr);
}

// ---------------- conversions (single launch) ----------------
struct CvtArgs {
    const float4* in[12];
    __half2* out[12];
    int n4[12];
};
__global__ void __launch_bounds__(256)
k_hall(CvtArgs a){
    int seg = blockIdx.y;
    const float4* in = a.in[seg];
    __half2* o = a.out[seg];
    int n4 = a.n4[seg];
    for(int i=blockIdx.x*256+threadIdx.x; i<n4; i+=gridDim.x*256){
        float4 v=in[i];
        o[2*i]   = __floats2half2_rn(v.x,v.y);
        o[2*i+1] = __floats2half2_rn(v.z,v.w);
    }
}

// ---------------- softmax normalize: parallel, register-resident stats -----
// grid (32, 32): CTA = 32-row chunk of one z; thread owns 4 columns.
__global__ void __launch_bounds__(256)
k_smnorm(const float* __restrict__ sc, const float2* __restrict__ part,
         half_t* __restrict__ o){
    int z=blockIdx.y, rc=blockIdx.x;
    int c0=threadIdx.x*4;
    float m[4], inv[4];
#pragma unroll
    for(int j=0;j<4;j++){
        float mm=-1e30f,s=0.f;
#pragma unroll
        for(int k=0;k<8;k++){
            float2 ps=part[((size_t)z*8+k)*Sz+c0+j];
            float nm=fmaxf(mm,ps.x);
            s=s*__expf(mm-nm)+ps.y*__expf(ps.x-nm);
            mm=nm;
        }
        m[j]=mm; inv[j]=1.0f/s;
    }
    size_t base=(size_t)z*Sz*Sz+(size_t)rc*32*Sz+c0;
#pragma unroll 4
    for(int r=0;r<32;r++){
        size_t ro=base+(size_t)r*Sz;
        float4 v=*(const float4*)(sc+ro);
        __half2 h0=__floats2half2_rn(__expf(v.x-m[0])*inv[0], __expf(v.y-m[1])*inv[1]);
        __half2 h1=__floats2half2_rn(__expf(v.z-m[2])*inv[2], __expf(v.w-m[3])*inv[3]);
        uint2 w;
        w.x=*(uint32_t*)&h0; w.y=*(uint32_t*)&h1;
        *(uint2*)(o+ro)=w;
    }
}

__global__ void __launch_bounds__(256)
k_addln(const float* __restrict__ xa,const float* __restrict__ xb,
        const float* __restrict__ gg,const float* __restrict__ bb,
        float* __restrict__ out, half_t* __restrict__ oh){
    int row=blockIdx.x;
    const float* xr=xa+(size_t)row*Dz;
    const float* yr=xb+(size_t)row*Dz;
    float v[8]; float s=0.f,s2=0.f;
#pragma unroll
    for(int i=0;i<8;i++){ int c=threadIdx.x+i*256; v[i]=xr[c]+yr[c]; s+=v[i]; s2+=v[i]*v[i]; }
    __shared__ float rs[8],rs2[8];
#pragma unroll
    for(int o=16;o>0;o>>=1){ s+=__shfl_xor_sync(0xffffffffu,s,o); s2+=__shfl_xor_sync(0xffffffffu,s2,o); }
    int wid=threadIdx.x>>5,lid=threadIdx.x&31;
    if(lid==0){ rs[wid]=s; rs2[wid]=s2; }
    __syncthreads();
    if(threadIdx.x<32){
        s=(threadIdx.x<8)?rs[threadIdx.x]:0.f; s2=(threadIdx.x<8)?rs2[threadIdx.x]:0.f;
#pragma unroll
        for(int o=4;o>0;o>>=1){ s+=__shfl_xor_sync(0xffffffffu,s,o); s2+=__shfl_xor_sync(0xffffffffu,s2,o); }
        if(threadIdx.x==0){ rs[0]=s; rs2[0]=s2; }
    }
    __syncthreads();
    float mean=rs[0]*(1.0f/Dz);
    float var=rs2[0]*(1.0f/Dz)-mean*mean;
    float inv=rsqrtf(var+1e-5f);
#pragma unroll
    for(int i=0;i<8;i++){
        int c=threadIdx.x+i*256;
        float o=(v[i]-mean)*inv*gg[c]+bb[c];
        out[(size_t)row*Dz+c]=o;
        if(oh) oh[(size_t)row*Dz+c]=__float2half_rn(o);
    }
}

// ---------------- launch ----------------
#define GA(v,s) do{ void* _p; cudaGetSymbolAddress(&_p,s); v=(decltype(v))_p; }while(0)

extern "C" void kernel_launch(void* const* d_in,const int* in_sizes,int n_in,
                              void* d_out,int out_size)
{
    const float* x   =(const float*)d_in[0];
    const float* enc =(const float*)d_in[1];
    const float* wq1 =(const float*)d_in[2];
    const float* wk1 =(const float*)d_in[3];
    const float* wv1 =(const float*)d_in[4];
    const float* bq1 =(const float*)d_in[5];
    const float* bk1 =(const float*)d_in[6];
    const float* bv1 =(const float*)d_in[7];
    const float* wp1 =(const float*)d_in[8];
    const float* bp1 =(const float*)d_in[9];
    const float* wq2 =(const float*)d_in[10];
    const float* wk2 =(const float*)d_in[11];
    const float* wv2 =(const float*)d_in[12];
    const float* bq2 =(const float*)d_in[13];
    const float* bk2 =(const float*)d_in[14];
    const float* bv2 =(const float*)d_in[15];
    const float* wp2 =(const float*)d_in[16];
    const float* bp2 =(const float*)d_in[17];
    const float* ln1g=(const float*)d_in[18];
    const float* ln1b=(const float*)d_in[19];
    const float* ln2g=(const float*)d_in[20];
    const float* ln2b=(const float*)d_in[21];
    const float* ln3g=(const float*)d_in[22];
    const float* ln3b=(const float*)d_in[23];
    const float* wff1=(const float*)d_in[24];
    const float* bff1=(const float*)d_in[25];
    const float* wff2=(const float*)d_in[26];
    const float* bff2=(const float*)d_in[27];
    float* out=(float*)d_out;

    float *sc,*tp,*r1,*r2; float2* part;
    half_t *xh,*eh,*h1,*h2,*qh,*kh,*vh,*ah,*ch,*fh,*w1,*w2,*pc,*Fc;
    GA(sc,g_sc); GA(tp,g_t); GA(r1,g_r1); GA(r2,g_r2); GA(part,g_part);
    GA(xh,g_xh); GA(eh,g_eh); GA(h1,g_1h); GA(h2,g_2h);
    GA(qh,g_qh); GA(kh,g_kh); GA(vh,g_vh); GA(ah,g_ah);
    GA(ch,g_ch); GA(fh,g_fh);
    GA(w1,g_w1c); GA(w2,g_w2c); GA(pc,g_pc); GA(Fc,g_Fc);

    cudaFuncSetAttribute(k_proj3,  cudaFuncAttributeMaxDynamicSharedMemorySize,SMB);
    cudaFuncSetAttribute(k_scores, cudaFuncAttributeMaxDynamicSharedMemorySize,SMB);
    cudaFuncSetAttribute(k_attnv,  cudaFuncAttributeMaxDynamicSharedMemorySize,SMB);
    cudaFuncSetAttribute(k_lin32,  cudaFuncAttributeMaxDynamicSharedMemorySize,SMB);
    cudaFuncSetAttribute(k_linrelu,cudaFuncAttributeMaxDynamicSharedMemorySize,SMB);

    // all fp32->fp16 casts in ONE launch
    CvtArgs ca;
    ca.in[0]=(const float4*)wq1;  ca.out[0]=(__half2*)w1;           ca.n4[0]=NW_H/4;
    ca.in[1]=(const float4*)wk1;  ca.out[1]=(__half2*)(w1+NW_H);    ca.n4[1]=NW_H/4;
    ca.in[2]=(const float4*)wv1;  ca.out[2]=(__half2*)(w1+2*NW_H);  ca.n4[2]=NW_H/4;
    ca.in[3]=(const float4*)wq2;  ca.out[3]=(__half2*)w2;           ca.n4[3]=NW_H/4;
    ca.in[4]=(const float4*)wk2;  ca.out[4]=(__half2*)(w2+NW_H);    ca.n4[4]=NW_H/4;
    ca.in[5]=(const float4*)wv2;  ca.out[5]=(__half2*)(w2+2*NW_H);  ca.n4[5]=NW_H/4;
    ca.in[6]=(const float4*)wp1;  ca.out[6]=(__half2*)pc;           ca.n4[6]=NW_P/4;
    ca.in[7]=(const float4*)wp2;  ca.out[7]=(__half2*)(pc+NW_P);    ca.n4[7]=NW_P/4;
    ca.in[8]=(const float4*)wff1; ca.out[8]=(__half2*)Fc;           ca.n4[8]=NW_F/4;
    ca.in[9]=(const float4*)wff2; ca.out[9]=(__half2*)(Fc+NW_F);    ca.n4[9]=NW_F/4;
    ca.in[10]=(const float4*)x;   ca.out[10]=(__half2*)xh;          ca.n4[10]=NX/4;
    ca.in[11]=(const float4*)enc; ca.out[11]=(__half2*)eh;          ca.n4[11]=NX/4;
    k_hall<<<dim3(512,12),256>>>(ca);

    dim3 gp3(Sz/128,3,Bz*Hz), gp(Sz/128,1,Bz*Hz), gs(Sz/128,Sz/128,Bz*Hz);
    dim3 gsm(32,Bz*Hz);
    dim3 gpp(2*Sz/128,Dz/128), gf1(2*Sz/128,DFFz/128);

    // ---- self attention ----
    k_proj3<<<gp3,256,SMB>>>(xh,xh,w1,bq1,bk1,bv1,qh,kh,vh);
    k_scores<<<gs,256,SMB>>>(qh,kh,sc,part);
    k_smnorm<<<gsm,256>>>(sc,part,ah);
    k_attnv<<<gp,256,SMB>>>(ah,vh,ch);
    k_lin32<<<gpp,256,SMB>>>(ch,Dz,pc,Dz,bp1,tp,Dz,Dz);
    k_addln<<<Bz*Sz,256>>>(x,tp,ln1g,ln1b,r1,h1);

    // ---- cross attention: q from encoder_output, k/v from x1 ----
    k_proj3<<<gp3,256,SMB>>>(eh,h1,w2,bq2,bk2,bv2,qh,kh,vh);
    k_scores<<<gs,256,SMB>>>(qh,kh,sc,part);
    k_smnorm<<<gsm,256>>>(sc,part,ah);
    k_attnv<<<gp,256,SMB>>>(ah,vh,ch);
    k_lin32<<<gpp,256,SMB>>>(ch,Dz,pc+NW_P,Dz,bp2,tp,Dz,Dz);
    k_addln<<<Bz*Sz,256>>>(r1,tp,ln2g,ln2b,r2,h2);

    // ---- feed forward (ldb = natural row stride of B: wff1->DFFz, wff2->Dz) ----
    k_linrelu<<<gf1,256,SMB>>>(h2,Dz,Fc,DFFz,bff1,fh,DFFz,Dz);
    k_lin32<<<gpp,256,SMB>>>(fh,DFFz,Fc+NW_F,Dz,bff2,tp,Dz,DFFz);
    k_addln<<<Bz*Sz,256>>>(r2,tp,ln3g,ln3b,out,nullptr);
}